// round 1
// baseline (speedup 1.0000x reference)
#include <cuda_runtime.h>
#include <cuda_bf16.h>
#include <cstdint>
#include <cstddef>

// Problem constants (fixed shapes from the reference)
#define NROWS   65536     // 16*64*64
#define VDIM    1024      // codebook size V
#define DDIM    256       // embedding dim D
#define M_TILE  64        // rows per CTA
#define KCH     64        // V-chunk per GEMM stage
#define PSTRIDE 1032      // probs shared stride in bf16 (1024 + 8 pad -> conflict-free frag loads)
#define BSTRIDE 72        // codebook tile shared stride in bf16 (64 + 8 pad)
#define BUF_ELEMS (DDIM * BSTRIDE)            // one B-tile buffer: 256*72 bf16 = 36864 B
#define PROB_ELEMS (M_TILE * PSTRIDE)         // 64*1032 bf16 = 132096 B
#define SMEM_BYTES (PROB_ELEMS * 2 + 2 * BUF_ELEMS * 2)  // 205824 B

// Static device scratch (allocation-free rule): codebook transposed+converted to bf16, [D][V]
__device__ __nv_bfloat16 g_cbT[DDIM * VDIM];
__device__ int g_tgt64;   // 1 if target_indices is int64, 0 if int32

// ---------------------------------------------------------------------------
// Prep kernel: transpose codebook fp32 [V][D] -> bf16 [D][V]; zero output;
// detect target dtype (int64 view has zero high words for indices < 1024).
// ---------------------------------------------------------------------------
__global__ void prep_kernel(const float* __restrict__ cb,
                            const void*  __restrict__ tgt,
                            float* __restrict__ out) {
    __shared__ float tile[32][33];
    int v0 = blockIdx.x * 32;
    int d0 = blockIdx.y * 32;
    int tx = threadIdx.x, ty = threadIdx.y;

    #pragma unroll
    for (int i = 0; i < 4; i++) {
        int v = ty + i * 8;
        tile[v][tx] = cb[(size_t)(v0 + v) * DDIM + d0 + tx];
    }
    __syncthreads();
    #pragma unroll
    for (int i = 0; i < 4; i++) {
        int d = ty + i * 8;
        g_cbT[(size_t)(d0 + d) * VDIM + v0 + tx] = __float2bfloat16(tile[tx][d]);
    }

    if (blockIdx.x == 0 && blockIdx.y == 0 && tx == 0 && ty == 0) {
        // dtype sniff: if int64, every odd int32 word (high half) is 0.
        const int* t = (const int*)tgt;
        int is64 = 1;
        for (int i = 0; i < 256; i++) {
            if (t[2 * i + 1] != 0) { is64 = 0; break; }
        }
        g_tgt64 = is64;
        out[0] = 0.0f;
    }
}

// ---------------------------------------------------------------------------
// Helpers
// ---------------------------------------------------------------------------
__device__ __forceinline__ void cp16(void* dst_smem, const void* src_gmem) {
    unsigned d = (unsigned)__cvta_generic_to_shared(dst_smem);
    asm volatile("cp.async.cg.shared.global [%0], [%1], 16;" :: "r"(d), "l"(src_gmem));
}

__device__ __forceinline__ void issue_b_tile(__nv_bfloat16* buf, int kc, int tid) {
    // Each thread: (d-row group, 16B k-vector). Warp covers 4 full d-rows coalesced.
    int dd = tid >> 3;        // 0..31
    int kv = tid & 7;         // 0..7 (8 * 8 bf16 = 64 bf16 per row)
    #pragma unroll
    for (int i = 0; i < 8; i++) {
        int d = dd + i * 32;
        cp16(buf + d * BSTRIDE + kv * 8,
             g_cbT + (size_t)d * VDIM + kc * KCH + kv * 8);
    }
}

__device__ __forceinline__ void mma16816(float (&c)[4], const unsigned (&a)[4],
                                         unsigned b0, unsigned b1) {
    asm volatile(
        "mma.sync.aligned.m16n8k16.row.col.f32.bf16.bf16.f32 "
        "{%0,%1,%2,%3}, {%4,%5,%6,%7}, {%8,%9}, {%0,%1,%2,%3};"
        : "+f"(c[0]), "+f"(c[1]), "+f"(c[2]), "+f"(c[3])
        : "r"(a[0]), "r"(a[1]), "r"(a[2]), "r"(a[3]), "r"(b0), "r"(b1));
}

// ---------------------------------------------------------------------------
// Main fused kernel: softmax -> bf16 GEMM vs codebook -> squared-error reduce
// Grid: NROWS / M_TILE = 1024 CTAs, 256 threads (8 warps).
// ---------------------------------------------------------------------------
__global__ void __launch_bounds__(256)
loss_kernel(const float* __restrict__ logits,
            const void*  __restrict__ tgt,
            const float* __restrict__ cb,
            float* __restrict__ out) {
    extern __shared__ char smem[];
    __nv_bfloat16* probs = (__nv_bfloat16*)smem;                       // [64][1032]
    __nv_bfloat16* bsh   = (__nv_bfloat16*)(smem + PROB_ELEMS * 2);    // 2 x [256][72]

    const int tid  = threadIdx.x;
    const int lane = tid & 31;
    const int wid  = tid >> 5;

    // Prefetch first codebook tile while we do the softmax.
    issue_b_tile(bsh, 0, tid);
    asm volatile("cp.async.commit_group;" ::: "memory");

    // ---------------- Phase 1: softmax of 64 rows (1 warp per row) ----------
    #pragma unroll 1
    for (int r = 0; r < 8; r++) {
        int lrow = wid * 8 + r;
        size_t gbase = ((size_t)blockIdx.x * M_TILE + lrow) * VDIM;
        const float4* src = (const float4*)(logits + gbase);

        float4 v[8];
        #pragma unroll
        for (int j = 0; j < 8; j++) v[j] = src[lane + 32 * j];

        float m = -3.4e38f;
        #pragma unroll
        for (int j = 0; j < 8; j++) {
            m = fmaxf(m, fmaxf(fmaxf(v[j].x, v[j].y), fmaxf(v[j].z, v[j].w)));
        }
        #pragma unroll
        for (int off = 16; off > 0; off >>= 1)
            m = fmaxf(m, __shfl_xor_sync(0xffffffffu, m, off));

        float s = 0.0f;
        #pragma unroll
        for (int j = 0; j < 8; j++) {
            v[j].x = __expf(v[j].x - m);
            v[j].y = __expf(v[j].y - m);
            v[j].z = __expf(v[j].z - m);
            v[j].w = __expf(v[j].w - m);
            s += v[j].x + v[j].y + v[j].z + v[j].w;
        }
        #pragma unroll
        for (int off = 16; off > 0; off >>= 1)
            s += __shfl_xor_sync(0xffffffffu, s, off);
        float inv = 1.0f / s;

        __nv_bfloat16* prow = probs + (size_t)lrow * PSTRIDE;
        #pragma unroll
        for (int j = 0; j < 8; j++) {
            __nv_bfloat162 h01 = __floats2bfloat162_rn(v[j].x * inv, v[j].y * inv);
            __nv_bfloat162 h23 = __floats2bfloat162_rn(v[j].z * inv, v[j].w * inv);
            uint2 pk;
            pk.x = *(unsigned*)&h01;
            pk.y = *(unsigned*)&h23;
            *(uint2*)(prow + lane * 4 + j * 128) = pk;
        }
    }

    // ---------------- Phase 2: GEMM probs[64,1024] x cbT -> pred[64,256] ----
    // Warp tile: 32 (M) x 64 (N). warp_m in {0,1}, warp_n in {0..3}.
    const int warp_m = wid & 1;
    const int warp_n = wid >> 1;

    float acc[2][8][4];
    #pragma unroll
    for (int mi = 0; mi < 2; mi++)
        #pragma unroll
        for (int nf = 0; nf < 8; nf++)
            #pragma unroll
            for (int q = 0; q < 4; q++) acc[mi][nf][q] = 0.0f;

    const int arow_base = warp_m * 32 + (lane >> 2);
    const int acol_sub  = (lane & 3) * 2;

    #pragma unroll 1
    for (int kc = 0; kc < VDIM / KCH; kc++) {
        if (kc + 1 < VDIM / KCH) {
            issue_b_tile(bsh + ((kc + 1) & 1) * BUF_ELEMS, kc + 1, tid);
            asm volatile("cp.async.commit_group;" ::: "memory");
            asm volatile("cp.async.wait_group 1;" ::: "memory");
        } else {
            asm volatile("cp.async.wait_group 0;" ::: "memory");
        }
        __syncthreads();

        const __nv_bfloat16* buf = bsh + (kc & 1) * BUF_ELEMS;

        #pragma unroll
        for (int ks = 0; ks < 4; ks++) {
            int kglob = kc * KCH + ks * 16;
            unsigned a[2][4];
            #pragma unroll
            for (int mi = 0; mi < 2; mi++) {
                const __nv_bfloat16* p0 =
                    probs + (size_t)(arow_base + mi * 16) * PSTRIDE + kglob + acol_sub;
                a[mi][0] = *(const unsigned*)(p0);
                a[mi][1] = *(const unsigned*)(p0 + 8 * PSTRIDE);
                a[mi][2] = *(const unsigned*)(p0 + 8);
                a[mi][3] = *(const unsigned*)(p0 + 8 * PSTRIDE + 8);
            }
            #pragma unroll
            for (int nf = 0; nf < 8; nf++) {
                int bn = warp_n * 64 + nf * 8 + (lane >> 2);
                const __nv_bfloat16* pb = buf + (size_t)bn * BSTRIDE + ks * 16 + acol_sub;
                unsigned b0 = *(const unsigned*)(pb);
                unsigned b1 = *(const unsigned*)(pb + 8);
                mma16816(acc[0][nf], a[0], b0, b1);
                mma16816(acc[1][nf], a[1], b0, b1);
            }
        }
        __syncthreads();
    }

    // ---------------- Phase 3: epilogue: (pred - codebook[target])^2 --------
    const int is64 = g_tgt64;
    const long long* t64 = (const long long*)tgt;
    const int*       t32 = (const int*)tgt;

    float lsum = 0.0f;
    #pragma unroll
    for (int mi = 0; mi < 2; mi++) {
        int r0 = blockIdx.x * M_TILE + warp_m * 32 + mi * 16 + (lane >> 2);
        int r1 = r0 + 8;
        int tg0 = is64 ? (int)t64[r0] : t32[r0];
        int tg1 = is64 ? (int)t64[r1] : t32[r1];
        const float* cb0 = cb + (size_t)tg0 * DDIM;
        const float* cb1 = cb + (size_t)tg1 * DDIM;
        #pragma unroll
        for (int nf = 0; nf < 8; nf++) {
            int col = warp_n * 64 + nf * 8 + (lane & 3) * 2;
            float2 g0 = *(const float2*)(cb0 + col);
            float2 g1 = *(const float2*)(cb1 + col);
            float d0 = acc[mi][nf][0] - g0.x;
            float d1 = acc[mi][nf][1] - g0.y;
            float d2 = acc[mi][nf][2] - g1.x;
            float d3 = acc[mi][nf][3] - g1.y;
            lsum += d0 * d0 + d1 * d1 + d2 * d2 + d3 * d3;
        }
    }
    #pragma unroll
    for (int off = 16; off > 0; off >>= 1)
        lsum += __shfl_xor_sync(0xffffffffu, lsum, off);

    __shared__ float sred[8];
    if (lane == 0) sred[wid] = lsum;
    __syncthreads();
    if (tid == 0) {
        float tot = 0.0f;
        #pragma unroll
        for (int i = 0; i < 8; i++) tot += sred[i];
        atomicAdd(out, tot * (1.0f / ((float)NROWS * (float)DDIM)));
    }
}

// ---------------------------------------------------------------------------
// Launch
// ---------------------------------------------------------------------------
extern "C" void kernel_launch(void* const* d_in, const int* in_sizes, int n_in,
                              void* d_out, int out_size) {
    // Identify inputs by element count (robust to ordering).
    const float* logits = nullptr;
    const void*  tgt    = nullptr;
    const float* cb     = nullptr;
    for (int i = 0; i < n_in; i++) {
        if (in_sizes[i] == NROWS * VDIM)      logits = (const float*)d_in[i];
        else if (in_sizes[i] == NROWS)        tgt    = d_in[i];
        else if (in_sizes[i] == VDIM * DDIM)  cb     = (const float*)d_in[i];
    }
    float* out = (float*)d_out;

    cudaFuncSetAttribute(loss_kernel,
                         cudaFuncAttributeMaxDynamicSharedMemorySize, SMEM_BYTES);

    dim3 pgrid(VDIM / 32, DDIM / 32);
    dim3 pblk(32, 8);
    prep_kernel<<<pgrid, pblk>>>(cb, tgt, out);

    loss_kernel<<<NROWS / M_TILE, 256, SMEM_BYTES>>>(logits, tgt, cb, out);
}

// round 2
// speedup vs baseline: 1.3080x; 1.3080x over previous
#include <cuda_runtime.h>
#include <cuda_bf16.h>
#include <cstdint>
#include <cstddef>

// Problem constants (fixed shapes)
#define NROWS   65536     // 16*64*64
#define VDIM    1024      // codebook size V
#define DDIM    256       // embedding dim D
#define M_TILE  128       // rows per CTA
#define NCTAS   (NROWS / M_TILE)   // 512
#define NTHREADS 512
#define KCH     64        // V-chunk per pipeline stage
#define NCHUNK  (VDIM / KCH)       // 16
#define ASTRIDE 72        // A tile smem stride bf16 (64 + 8 pad)
#define BSTRIDE 72        // B tile smem stride bf16
#define A_ELEMS (M_TILE * ASTRIDE)   // 128*72
#define B_ELEMS (DDIM * BSTRIDE)     // 256*72
#define SMEM_BYTES ((2 * A_ELEMS + 2 * B_ELEMS) * 2)   // 110592 B dynamic

// Static device scratch: codebook transposed+converted to bf16, [D][V]
__device__ __nv_bfloat16 g_cbT[DDIM * VDIM];
__device__ int g_tgt64;

// ---------------------------------------------------------------------------
// Prep: transpose codebook fp32 [V][D] -> bf16 [D][V]; zero out; dtype sniff.
// ---------------------------------------------------------------------------
__global__ void prep_kernel(const float* __restrict__ cb,
                            const void*  __restrict__ tgt,
                            float* __restrict__ out) {
    __shared__ float tile[32][33];
    int v0 = blockIdx.x * 32;
    int d0 = blockIdx.y * 32;
    int tx = threadIdx.x, ty = threadIdx.y;

    #pragma unroll
    for (int i = 0; i < 4; i++) {
        int v = ty + i * 8;
        tile[v][tx] = cb[(size_t)(v0 + v) * DDIM + d0 + tx];
    }
    __syncthreads();
    #pragma unroll
    for (int i = 0; i < 4; i++) {
        int d = ty + i * 8;
        g_cbT[(size_t)(d0 + d) * VDIM + v0 + tx] = __float2bfloat16(tile[tx][d]);
    }

    if (blockIdx.x == 0 && blockIdx.y == 0 && tx == 0 && ty == 0) {
        const int* t = (const int*)tgt;
        int is64 = 1;
        for (int i = 0; i < 256; i++) {
            if (t[2 * i + 1] != 0) { is64 = 0; break; }
        }
        g_tgt64 = is64;
        out[0] = 0.0f;
    }
}

// ---------------------------------------------------------------------------
// Helpers
// ---------------------------------------------------------------------------
__device__ __forceinline__ void cp16(void* dst_smem, const void* src_gmem) {
    unsigned d = (unsigned)__cvta_generic_to_shared(dst_smem);
    asm volatile("cp.async.cg.shared.global [%0], [%1], 16;" :: "r"(d), "l"(src_gmem));
}

// Load one B chunk [256 D rows x 64 k] of bf16 cbT into smem (512 threads).
__device__ __forceinline__ void issue_b_tile(__nv_bfloat16* buf, int kc, int tid) {
    int dd = tid >> 3;       // 0..63
    int kv = tid & 7;        // 0..7  (8 x 8 bf16 = 64 bf16 per row)
    #pragma unroll
    for (int i = 0; i < 4; i++) {
        int d = dd + i * 64;
        cp16(buf + d * BSTRIDE + kv * 8,
             g_cbT + (size_t)d * VDIM + kc * KCH + kv * 8);
    }
}

__device__ __forceinline__ void mma16816(float (&c)[4], const unsigned (&a)[4],
                                         unsigned b0, unsigned b1) {
    asm volatile(
        "mma.sync.aligned.m16n8k16.row.col.f32.bf16.bf16.f32 "
        "{%0,%1,%2,%3}, {%4,%5,%6,%7}, {%8,%9}, {%0,%1,%2,%3};"
        : "+f"(c[0]), "+f"(c[1]), "+f"(c[2]), "+f"(c[3])
        : "r"(a[0]), "r"(a[1]), "r"(a[2]), "r"(a[3]), "r"(b0), "r"(b1));
}

// ---------------------------------------------------------------------------
// Fused streaming kernel: exp(logits) chunked GEMM with deferred softmax
// normalization (pred = (exp @ cb) / rowsum), then squared-error reduce.
// Grid: 512 CTAs x 512 threads (16 warps, 4M x 4N warp grid).
// ---------------------------------------------------------------------------
__global__ void __launch_bounds__(NTHREADS)
loss_kernel(const float* __restrict__ logits,
            const void*  __restrict__ tgt,
            const float* __restrict__ cb,
            float* __restrict__ out) {
    extern __shared__ char smem[];
    __nv_bfloat16* Ash = (__nv_bfloat16*)smem;                         // 2 x [128][72]
    __nv_bfloat16* Bsh = (__nv_bfloat16*)(smem + 2 * A_ELEMS * 2);     // 2 x [256][72]
    __shared__ float rowinv[M_TILE];
    __shared__ float sred[16];

    const int tid  = threadIdx.x;
    const int lane = tid & 31;
    const int wid  = tid >> 5;
    const int warp_m = wid & 3;    // 0..3
    const int warp_n = wid >> 2;   // 0..3

    // Per-thread logits slice: 4 float4 per chunk.
    // row_i = (tid>>4) + 32*i,  v4 = tid&15 (within-chunk float4 index)
    const int rbase = tid >> 4;        // 0..31
    const int v4    = tid & 15;        // 0..15
    const float4* src4 = (const float4*)(logits + (size_t)blockIdx.x * M_TILE * VDIM);
    // float4s per row = 256; chunk kc spans [kc*16, kc*16+16)

    // Prologue: B chunk 0 + logits chunk 0
    issue_b_tile(Bsh, 0, tid);
    asm volatile("cp.async.commit_group;" ::: "memory");

    float4 cur[4], nxt[4];
    #pragma unroll
    for (int i = 0; i < 4; i++)
        cur[i] = src4[(size_t)(rbase + 32 * i) * 256 + v4];

    float rs[4] = {0.f, 0.f, 0.f, 0.f};

    float acc[2][8][4];
    #pragma unroll
    for (int mi = 0; mi < 2; mi++)
        #pragma unroll
        for (int nf = 0; nf < 8; nf++)
            #pragma unroll
            for (int q = 0; q < 4; q++) acc[mi][nf][q] = 0.0f;

    const int arow_base = warp_m * 32 + (lane >> 2);
    const int acol_sub  = (lane & 3) * 2;

    #pragma unroll 1
    for (int kc = 0; kc < NCHUNK; kc++) {
        // Prefetch next logits chunk (HBM latency hidden under exp + MMA)
        if (kc + 1 < NCHUNK) {
            #pragma unroll
            for (int i = 0; i < 4; i++)
                nxt[i] = src4[(size_t)(rbase + 32 * i) * 256 + (kc + 1) * 16 + v4];
        }

        // exp + rowsum + bf16 store into A[kc&1]
        __nv_bfloat16* a = Ash + (kc & 1) * A_ELEMS;
        #pragma unroll
        for (int i = 0; i < 4; i++) {
            float e0 = __expf(cur[i].x);
            float e1 = __expf(cur[i].y);
            float e2 = __expf(cur[i].z);
            float e3 = __expf(cur[i].w);
            rs[i] += (e0 + e1) + (e2 + e3);
            __nv_bfloat162 h01 = __floats2bfloat162_rn(e0, e1);
            __nv_bfloat162 h23 = __floats2bfloat162_rn(e2, e3);
            uint2 pk;
            pk.x = *(unsigned*)&h01;
            pk.y = *(unsigned*)&h23;
            *(uint2*)(a + (rbase + 32 * i) * ASTRIDE + v4 * 4) = pk;
        }

        // B[kc] must be resident before MMA
        asm volatile("cp.async.wait_group 0;" ::: "memory");
        __syncthreads();

        // Kick off B chunk kc+1 (safe: previous reader of that buffer done)
        if (kc + 1 < NCHUNK) {
            issue_b_tile(Bsh + ((kc + 1) & 1) * B_ELEMS, kc + 1, tid);
            asm volatile("cp.async.commit_group;" ::: "memory");
        }

        // MMA: A[128x64] x B[64x256]
        const __nv_bfloat16* bb = Bsh + (kc & 1) * B_ELEMS;
        #pragma unroll
        for (int ks = 0; ks < 4; ks++) {
            unsigned afr[2][4];
            #pragma unroll
            for (int mi = 0; mi < 2; mi++) {
                const __nv_bfloat16* p0 =
                    a + (size_t)(arow_base + mi * 16) * ASTRIDE + ks * 16 + acol_sub;
                afr[mi][0] = *(const unsigned*)(p0);
                afr[mi][1] = *(const unsigned*)(p0 + 8 * ASTRIDE);
                afr[mi][2] = *(const unsigned*)(p0 + 8);
                afr[mi][3] = *(const unsigned*)(p0 + 8 * ASTRIDE + 8);
            }
            #pragma unroll
            for (int nf = 0; nf < 8; nf++) {
                int bn = warp_n * 64 + nf * 8 + (lane >> 2);
                const __nv_bfloat16* pb = bb + (size_t)bn * BSTRIDE + ks * 16 + acol_sub;
                unsigned b0 = *(const unsigned*)(pb);
                unsigned b1 = *(const unsigned*)(pb + 8);
                mma16816(acc[0][nf], afr[0], b0, b1);
                mma16816(acc[1][nf], afr[1], b0, b1);
            }
        }

        #pragma unroll
        for (int i = 0; i < 4; i++) cur[i] = nxt[i];
    }

    // Row-sum reduction across the 16 threads sharing each row (within warp
    // halves: group of 16 consecutive tids), then publish 1/sum.
    #pragma unroll
    for (int i = 0; i < 4; i++) {
        float s = rs[i];
        s += __shfl_xor_sync(0xffffffffu, s, 1);
        s += __shfl_xor_sync(0xffffffffu, s, 2);
        s += __shfl_xor_sync(0xffffffffu, s, 4);
        s += __shfl_xor_sync(0xffffffffu, s, 8);
        if ((tid & 15) == 0) rowinv[rbase + 32 * i] = 1.0f / s;
    }
    __syncthreads();

    // Epilogue: pred = acc * rowinv; loss += (pred - cb[target])^2
    const int is64 = g_tgt64;
    const long long* t64 = (const long long*)tgt;
    const int*       t32 = (const int*)tgt;

    float lsum = 0.0f;
    #pragma unroll
    for (int mi = 0; mi < 2; mi++) {
        int lr0 = warp_m * 32 + mi * 16 + (lane >> 2);
        int lr1 = lr0 + 8;
        int r0 = blockIdx.x * M_TILE + lr0;
        int r1 = blockIdx.x * M_TILE + lr1;
        float inv0 = rowinv[lr0];
        float inv1 = rowinv[lr1];
        int tg0 = is64 ? (int)t64[r0] : t32[r0];
        int tg1 = is64 ? (int)t64[r1] : t32[r1];
        const float* cb0 = cb + (size_t)tg0 * DDIM;
        const float* cb1 = cb + (size_t)tg1 * DDIM;
        #pragma unroll
        for (int nf = 0; nf < 8; nf++) {
            int col = warp_n * 64 + nf * 8 + (lane & 3) * 2;
            float2 g0 = *(const float2*)(cb0 + col);
            float2 g1 = *(const float2*)(cb1 + col);
            float d0 = acc[mi][nf][0] * inv0 - g0.x;
            float d1 = acc[mi][nf][1] * inv0 - g0.y;
            float d2 = acc[mi][nf][2] * inv1 - g1.x;
            float d3 = acc[mi][nf][3] * inv1 - g1.y;
            lsum += d0 * d0 + d1 * d1 + d2 * d2 + d3 * d3;
        }
    }
    #pragma unroll
    for (int off = 16; off > 0; off >>= 1)
        lsum += __shfl_xor_sync(0xffffffffu, lsum, off);

    if (lane == 0) sred[wid] = lsum;
    __syncthreads();
    if (tid == 0) {
        float tot = 0.0f;
        #pragma unroll
        for (int i = 0; i < 16; i++) tot += sred[i];
        atomicAdd(out, tot * (1.0f / ((float)NROWS * (float)DDIM)));
    }
}

// ---------------------------------------------------------------------------
// Launch
// ---------------------------------------------------------------------------
extern "C" void kernel_launch(void* const* d_in, const int* in_sizes, int n_in,
                              void* d_out, int out_size) {
    const float* logits = nullptr;
    const void*  tgt    = nullptr;
    const float* cb     = nullptr;
    for (int i = 0; i < n_in; i++) {
        if (in_sizes[i] == NROWS * VDIM)      logits = (const float*)d_in[i];
        else if (in_sizes[i] == NROWS)        tgt    = d_in[i];
        else if (in_sizes[i] == VDIM * DDIM)  cb     = (const float*)d_in[i];
    }
    float* out = (float*)d_out;

    cudaFuncSetAttribute(loss_kernel,
                         cudaFuncAttributeMaxDynamicSharedMemorySize, SMEM_BYTES);

    dim3 pgrid(VDIM / 32, DDIM / 32);
    dim3 pblk(32, 8);
    prep_kernel<<<pgrid, pblk>>>(cb, tgt, out);

    loss_kernel<<<NCTAS, NTHREADS, SMEM_BYTES>>>(logits, tgt, cb, out);
}

// round 4
// speedup vs baseline: 1.3916x; 1.0639x over previous
#include <cuda_runtime.h>
#include <cuda_bf16.h>
#include <cstdint>
#include <cstddef>

// Problem constants
#define NROWS   65536
#define VDIM    1024
#define DDIM    256
#define M_TILE  64
#define NCTAS   (NROWS / M_TILE)     // 1024
#define NTHREADS 256
#define KCH     64
#define NCHUNK  (VDIM / KCH)         // 16
#define ASTRIDE 72                   // bf16 elems per A smem row (144B, LDSM conflict-free)
#define BSTRIDE 72
#define A_ELEMS (M_TILE * ASTRIDE)   // 64*72
#define B_ELEMS (DDIM * BSTRIDE)     // 256*72
#define SMEM_BYTES ((2 * A_ELEMS + 2 * B_ELEMS) * 2)   // 92160 B -> 2 CTAs/SM

// Static scratch: codebook transposed+converted to bf16, [D][V]
__device__ __nv_bfloat16 g_cbT[DDIM * VDIM];
__device__ int g_tgt64;

// ---------------------------------------------------------------------------
// Prep: transpose codebook fp32 [V][D] -> bf16 [D][V]; zero out; dtype sniff.
// ---------------------------------------------------------------------------
__global__ void prep_kernel(const float* __restrict__ cb,
                            const void*  __restrict__ tgt,
                            float* __restrict__ out) {
    __shared__ float tile[32][33];
    int v0 = blockIdx.x * 32;
    int d0 = blockIdx.y * 32;
    int tx = threadIdx.x, ty = threadIdx.y;

    #pragma unroll
    for (int i = 0; i < 4; i++) {
        int v = ty + i * 8;
        tile[v][tx] = cb[(size_t)(v0 + v) * DDIM + d0 + tx];
    }
    __syncthreads();
    #pragma unroll
    for (int i = 0; i < 4; i++) {
        int d = ty + i * 8;
        g_cbT[(size_t)(d0 + d) * VDIM + v0 + tx] = __float2bfloat16(tile[tx][d]);
    }

    if (blockIdx.x == 0 && blockIdx.y == 0 && tx == 0 && ty == 0) {
        const int* t = (const int*)tgt;
        int is64 = 1;
        for (int i = 0; i < 256; i++) {
            if (t[2 * i + 1] != 0) { is64 = 0; break; }
        }
        g_tgt64 = is64;
        out[0] = 0.0f;
    }
}

// ---------------------------------------------------------------------------
// Helpers
// ---------------------------------------------------------------------------
__device__ __forceinline__ uint32_t smem_u32(const void* p) {
    uint32_t a;
    asm("{ .reg .u64 t; cvta.to.shared.u64 t, %1; cvt.u32.u64 %0, t; }" : "=r"(a) : "l"(p));
    return a;
}

__device__ __forceinline__ void cp16(uint32_t dst_smem, const void* src_gmem) {
    asm volatile("cp.async.cg.shared.global [%0], [%1], 16;" :: "r"(dst_smem), "l"(src_gmem));
}

__device__ __forceinline__ void ldsm_x4(uint32_t (&r)[4], uint32_t addr) {
    asm volatile("ldmatrix.sync.aligned.m8n8.x4.shared.b16 {%0,%1,%2,%3}, [%4];"
                 : "=r"(r[0]), "=r"(r[1]), "=r"(r[2]), "=r"(r[3]) : "r"(addr));
}

__device__ __forceinline__ void mma16816(float (&c)[4], const uint32_t (&a)[4],
                                         uint32_t b0, uint32_t b1) {
    asm volatile(
        "mma.sync.aligned.m16n8k16.row.col.f32.bf16.bf16.f32 "
        "{%0,%1,%2,%3}, {%4,%5,%6,%7}, {%8,%9}, {%0,%1,%2,%3};"
        : "+f"(c[0]), "+f"(c[1]), "+f"(c[2]), "+f"(c[3])
        : "r"(a[0]), "r"(a[1]), "r"(a[2]), "r"(a[3]), "r"(b0), "r"(b1));
}

// ---------------------------------------------------------------------------
// Fused streaming kernel: exp(logits) chunks -> mma.sync GEMM (deferred
// softmax normalization) -> squared-error reduce.
// Grid: 1024 CTAs x 256 threads (8 warps, 2M x 4N). 2 CTAs per SM.
// ---------------------------------------------------------------------------
__global__ void __launch_bounds__(NTHREADS, 2)
loss_kernel(const float* __restrict__ logits,
            const void*  __restrict__ tgt,
            const float* __restrict__ cb,
            float* __restrict__ out) {
    extern __shared__ char smem[];
    __nv_bfloat16* Ash = (__nv_bfloat16*)smem;                       // 2 x [64][72]
    __nv_bfloat16* Bsh = (__nv_bfloat16*)(smem + 2 * A_ELEMS * 2);   // 2 x [256][72]
    __shared__ float rowinv[M_TILE];
    __shared__ float sred[8];

    const int tid  = threadIdx.x;
    const int lane = tid & 31;
    const int wid  = tid >> 5;
    const int warp_m = wid & 1;    // 0..1
    const int warp_n = wid >> 1;   // 0..3

    // Per-thread logits slice: row = tid>>2 (0..63), quarter q = tid&3.
    const int row = tid >> 2;
    const int q   = tid & 3;
    const float4* src4 = (const float4*)(logits + (size_t)blockIdx.x * M_TILE * VDIM);
    const size_t rowbase4 = (size_t)row * (VDIM / 4);

    const uint32_t a_smem = smem_u32(Ash);
    const uint32_t b_smem = smem_u32(Bsh);

    // ldmatrix source addresses (within a buffer; buffer offset added per chunk)
    // A x4: row = m0 + (lane&15), kcol byte = ((lane>>4)<<3)*2
    const uint32_t a_lds_off =
        (uint32_t)((warp_m * 32 + (lane & 15)) * (ASTRIDE * 2) + ((lane >> 4) << 4));
    // B x4: row = n0 + (lane&7) + ((lane>>4)<<3), k byte = (((lane>>3)&1)<<3)*2
    const uint32_t b_lds_off =
        (uint32_t)(((lane & 7) + ((lane >> 4) << 3)) * (BSTRIDE * 2) + (((lane >> 3) & 1) << 4));

    // Prologue: B chunk 0 + logits chunk 0
    {
        #pragma unroll
        for (int i = 0; i < 8; i++) {
            int idx = tid + i * NTHREADS;    // 0..2047
            int n   = idx >> 3;
            int kv  = idx & 7;
            cp16(b_smem + n * (BSTRIDE * 2) + kv * 16,
                 g_cbT + (size_t)n * VDIM + kv * 8);
        }
        asm volatile("cp.async.commit_group;" ::: "memory");
    }

    float4 cur[4], nxt[4];
    #pragma unroll
    for (int j = 0; j < 4; j++) cur[j] = src4[rowbase4 + q * 4 + j];

    float rs = 0.0f;

    float acc[2][8][4];
    #pragma unroll
    for (int mi = 0; mi < 2; mi++)
        #pragma unroll
        for (int nf = 0; nf < 8; nf++)
            #pragma unroll
            for (int x = 0; x < 4; x++) acc[mi][nf][x] = 0.0f;

    #pragma unroll 1
    for (int kc = 0; kc < NCHUNK; kc++) {
        const int buf = kc & 1;

        // Prefetch next logits chunk (HBM hidden under exp + MMA).
        if (kc + 1 < NCHUNK) {
            #pragma unroll
            for (int j = 0; j < 4; j++)
                nxt[j] = src4[rowbase4 + (kc + 1) * 16 + q * 4 + j];
        }

        // exp + rowsum + bf16 store into A[buf].
        __nv_bfloat16* a = Ash + buf * A_ELEMS;
        #pragma unroll
        for (int j = 0; j < 4; j++) {
            float e0 = __expf(cur[j].x);
            float e1 = __expf(cur[j].y);
            float e2 = __expf(cur[j].z);
            float e3 = __expf(cur[j].w);
            rs += (e0 + e1) + (e2 + e3);
            __nv_bfloat162 h01 = __floats2bfloat162_rn(e0, e1);
            __nv_bfloat162 h23 = __floats2bfloat162_rn(e2, e3);
            uint2 pk;
            pk.x = *(unsigned*)&h01;
            pk.y = *(unsigned*)&h23;
            *(uint2*)((char*)a + row * (ASTRIDE * 2) + q * 32 + j * 8) = pk;
        }

        // B[kc] must be resident; A[buf] stores visible.
        asm volatile("cp.async.wait_group 0;" ::: "memory");
        __syncthreads();

        // Kick off B chunk kc+1 into the other buffer (its readers are done).
        if (kc + 1 < NCHUNK) {
            uint32_t bdst = b_smem + (buf ^ 1) * (B_ELEMS * 2);
            #pragma unroll
            for (int i = 0; i < 8; i++) {
                int idx = tid + i * NTHREADS;
                int n   = idx >> 3;
                int kv  = idx & 7;
                cp16(bdst + n * (BSTRIDE * 2) + kv * 16,
                     g_cbT + (size_t)n * VDIM + (kc + 1) * KCH + kv * 8);
            }
            asm volatile("cp.async.commit_group;" ::: "memory");
        }

        // MMA: A[64x64] x B[64x256] via ldmatrix fragments.
        const uint32_t a_buf = a_smem + buf * (A_ELEMS * 2) + a_lds_off;
        const uint32_t b_buf = b_smem + buf * (B_ELEMS * 2) + b_lds_off;

        #pragma unroll
        for (int ks = 0; ks < 4; ks++) {
            uint32_t afr[2][4];
            ldsm_x4(afr[0], a_buf + ks * 32);                       // rows m0..m0+15
            ldsm_x4(afr[1], a_buf + 16 * (ASTRIDE * 2) + ks * 32);  // rows m0+16..31? no:
            // NOTE: warp_m*32 covers 32 rows; afr[1] is rows +16.
            #pragma unroll
            for (int nb = 0; nb < 4; nb++) {                        // n-blocks of 16
                uint32_t bfr[4];
                ldsm_x4(bfr, b_buf + (warp_n * 64 + nb * 16) * (BSTRIDE * 2) + ks * 32);
                mma16816(acc[0][nb * 2 + 0], afr[0], bfr[0], bfr[1]);
                mma16816(acc[0][nb * 2 + 1], afr[0], bfr[2], bfr[3]);
                mma16816(acc[1][nb * 2 + 0], afr[1], bfr[0], bfr[1]);
                mma16816(acc[1][nb * 2 + 1], afr[1], bfr[2], bfr[3]);
            }
        }

        #pragma unroll
        for (int j = 0; j < 4; j++) cur[j] = nxt[j];
    }

    // Row-sum reduce across the 4 threads sharing a row.
    {
        float s = rs;
        s += __shfl_xor_sync(0xffffffffu, s, 1);
        s += __shfl_xor_sync(0xffffffffu, s, 2);
        if (q == 0) rowinv[row] = 1.0f / s;
    }
    __syncthreads();

    // Epilogue: pred = acc * rowinv; loss += (pred - cb[target])^2
    const int is64 = g_tgt64;
    const long long* t64 = (const long long*)tgt;
    const int*       t32 = (const int*)tgt;

    float lsum = 0.0f;
    #pragma unroll
    for (int mi = 0; mi < 2; mi++) {
        int lr0 = warp_m * 32 + mi * 16 + (lane >> 2);
        int lr1 = lr0 + 8;
        int r0 = blockIdx.x * M_TILE + lr0;
        int r1 = blockIdx.x * M_TILE + lr1;
        float inv0 = rowinv[lr0];
        float inv1 = rowinv[lr1];
        int tg0 = is64 ? (int)t64[r0] : t32[r0];
        int tg1 = is64 ? (int)t64[r1] : t32[r1];
        const float* cb0 = cb + (size_t)tg0 * DDIM;
        const float* cb1 = cb + (size_t)tg1 * DDIM;
        #pragma unroll
        for (int nf = 0; nf < 8; nf++) {
            int col = warp_n * 64 + nf * 8 + (lane & 3) * 2;
            float2 g0 = *(const float2*)(cb0 + col);
            float2 g1 = *(const float2*)(cb1 + col);
            float d0 = acc[mi][nf][0] * inv0 - g0.x;
            float d1 = acc[mi][nf][1] * inv0 - g0.y;
            float d2 = acc[mi][nf][2] * inv1 - g1.x;
            float d3 = acc[mi][nf][3] * inv1 - g1.y;
            lsum += d0 * d0 + d1 * d1 + d2 * d2 + d3 * d3;
        }
    }
    #pragma unroll
    for (int off = 16; off > 0; off >>= 1)
        lsum += __shfl_xor_sync(0xffffffffu, lsum, off);

    if (lane == 0) sred[wid] = lsum;
    __syncthreads();
    if (tid == 0) {
        float tot = 0.0f;
        #pragma unroll
        for (int i = 0; i < 8; i++) tot += sred[i];
        atomicAdd(out, tot * (1.0f / ((float)NROWS * (float)DDIM)));
    }
}

// ---------------------------------------------------------------------------
// Launch
// ---------------------------------------------------------------------------
extern "C" void kernel_launch(void* const* d_in, const int* in_sizes, int n_in,
                              void* d_out, int out_size) {
    const float* logits = nullptr;
    const void*  tgt    = nullptr;
    const float* cb     = nullptr;
    for (int i = 0; i < n_in; i++) {
        if (in_sizes[i] == NROWS * VDIM)      logits = (const float*)d_in[i];
        else if (in_sizes[i] == NROWS)        tgt    = d_in[i];
        else if (in_sizes[i] == VDIM * DDIM)  cb     = (const float*)d_in[i];
    }
    float* out = (float*)d_out;

    cudaFuncSetAttribute(loss_kernel,
                         cudaFuncAttributeMaxDynamicSharedMemorySize, SMEM_BYTES);

    dim3 pgrid(VDIM / 32, DDIM / 32);
    dim3 pblk(32, 8);
    prep_kernel<<<pgrid, pblk>>>(cb, tgt, out);

    loss_kernel<<<NCTAS, NTHREADS, SMEM_BYTES>>>(logits, tgt, cb, out);
}